// round 1
// baseline (speedup 1.0000x reference)
#include <cuda_runtime.h>
#include <cuda_bf16.h>

// Problem constants (fixed by the reference)
#define BATCH 16
#define MCTRL 64          // control points per axis
#define DEG   3           // degree (P == Q == 3)
#define LKNOT 68          // M + P + 1
#define OUTT  256         // OUT_U == OUT_V

// Scratch: basis values and spans for the (shared) u/v parameter axis.
// V is built from knot_u in the reference and v-linspace == u-linspace,
// so Nv == Nu and vspan == uspan — compute once, use for both axes.
__device__ float4 g_basis[BATCH][OUTT];   // 4 basis values per (b, t)
__device__ int    g_span [BATCH][OUTT];

// ---------------------------------------------------------------------------
// Kernel 1: normalized knots -> span + Cox-de Boor basis per (batch, t)
// ---------------------------------------------------------------------------
__global__ void basis_kernel(const float* __restrict__ knot_u) {
    const int b = blockIdx.x;
    __shared__ float U[LKNOT];

    if (threadIdx.x == 0) {
        // cumsum + normalize: U = (cumsum(k) - c0) / (cN - c0)
        float cs[LKNOT];
        float c = 0.0f;
        #pragma unroll 1
        for (int i = 0; i < LKNOT; i++) {
            c += knot_u[b * LKNOT + i];
            cs[i] = c;
        }
        const float c0  = cs[0];
        const float inv = 1.0f / (cs[LKNOT - 1] - c0);
        #pragma unroll 1
        for (int i = 0; i < LKNOT; i++) U[i] = (cs[i] - c0) * inv;
    }
    __syncthreads();

    const int   i    = threadIdx.x;           // eval point index 0..255
    const float step = (1.0f - 2e-5f) / (float)(OUTT - 1);
    const float t    = 1e-5f + (float)i * step;

    // find_span: argmin over s in [DEG, LKNOT-DEG-1] of (d>1e-8 ? d : 1.0),
    // first occurrence wins (strict <), matching jnp.argmin.
    float best = 1e30f;
    int   span = DEG;
    #pragma unroll 1
    for (int s = DEG; s <= LKNOT - DEG - 1; s++) {   // s = 3..64
        float d    = t - U[s];
        float cand = (d > 1e-8f) ? d : 1.0f;
        if (cand < best) { best = cand; span = s; }
    }

    // Cox-de Boor recursion (replicates reference op order, incl. the
    // (K1 - t) + (t - K2) denominator).
    float Ni[DEG + 1];
    Ni[0] = 1.0f;
    #pragma unroll
    for (int k = 1; k <= DEG; k++) {
        float saved = 0.0f;
        #pragma unroll
        for (int r = 0; r < k; r++) {
            float K1   = U[span + r + 1];
            float K2   = U[span + 1 - k + r];
            float temp = Ni[r] / ((K1 - t) + (t - K2));
            Ni[r]      = saved + (K1 - t) * temp;
            saved      = (t - K2) * temp;
        }
        Ni[k] = saved;
    }

    g_span[b][i]  = span;
    g_basis[b][i] = make_float4(Ni[0], Ni[1], Ni[2], Ni[3]);
}

// ---------------------------------------------------------------------------
// Kernel 2: tensor-product surface evaluation.
// One block per (u, b); 256 threads = the v row. Stage the 4 active control
// rows (4 x 64 x float4 = 4KB) in shared; each thread does 4x4 weighted sum.
// ---------------------------------------------------------------------------
__global__ void __launch_bounds__(OUTT) eval_kernel(
    const float* __restrict__ ctrl, float* __restrict__ out) {
    const int u = blockIdx.x;
    const int b = blockIdx.y;
    const int v = threadIdx.x;

    __shared__ float4 sc[DEG + 1][MCTRL];   // 4 ctrl rows, full width
    __shared__ float  sNu[DEG + 1];
    __shared__ int    s_su;

    if (threadIdx.x == 0) {
        s_su = g_span[b][u] - DEG;          // first active row index (0..60)
        float4 nu = g_basis[b][u];
        sNu[0] = nu.x; sNu[1] = nu.y; sNu[2] = nu.z; sNu[3] = nu.w;
    }
    __syncthreads();

    const int su = s_su;
    const float4* cp = (const float4*)ctrl + (size_t)b * MCTRL * MCTRL;

    // 256 threads load 4*64 = 256 float4s: exactly one each.
    {
        int idx = threadIdx.x;
        int l = idx >> 6;          // 0..3
        int j = idx & 63;          // 0..63
        sc[l][j] = cp[(su + l) * MCTRL + j];
    }

    // Per-thread v-axis basis + span (coalesced float4 loads from global).
    const float4 nv = g_basis[b][v];
    const int    sv = g_span[b][v] - DEG;
    const float  nvr[4] = {nv.x, nv.y, nv.z, nv.w};

    __syncthreads();

    float ax = 0.0f, ay = 0.0f, az = 0.0f;
    #pragma unroll
    for (int l = 0; l <= DEG; l++) {
        const float a = sNu[l];
        #pragma unroll
        for (int r = 0; r <= DEG; r++) {
            const float  w = a * nvr[r];
            const float4 c = sc[l][sv + r];
            ax = fmaf(w, c.x, ax);
            ay = fmaf(w, c.y, ay);
            az = fmaf(w, c.z, az);
        }
    }

    float* o = out + ((size_t)(b * OUTT + u) * OUTT + v) * 3;
    o[0] = ax;
    o[1] = ay;
    o[2] = az;
}

// ---------------------------------------------------------------------------
// Launch: inputs are [ctrl_pts, knot_u, knot_v] per setup_inputs order.
// knot_v is unused (the reference builds V from knot_u).
// ---------------------------------------------------------------------------
extern "C" void kernel_launch(void* const* d_in, const int* in_sizes, int n_in,
                              void* d_out, int out_size) {
    const float* ctrl   = (const float*)d_in[0];   // [16,64,64,4]
    const float* knot_u = (const float*)d_in[1];   // [16,68]
    (void)in_sizes; (void)n_in;

    float* out = (float*)d_out;                    // [16,256,256,3]

    basis_kernel<<<BATCH, OUTT>>>(knot_u);

    dim3 grid(OUTT, BATCH);
    eval_kernel<<<grid, OUTT>>>(ctrl, out);
    (void)out_size;
}

// round 3
// speedup vs baseline: 1.6333x; 1.6333x over previous
#include <cuda_runtime.h>
#include <cuda_bf16.h>

// Problem constants (fixed by the reference)
#define BATCH 16
#define MCTRL 64          // control points per axis
#define DEG   3           // degree (P == Q == 3)
#define LKNOT 68          // M + P + 1
#define OUTT  256         // OUT_U == OUT_V

// Basis values and spans for the shared u/v parameter axis.
// Reference builds V from knot_u and v-linspace == u-linspace, so
// Nv == Nu and vspan == uspan — compute once, use for both axes.
__device__ float4 g_basis[BATCH][OUTT];
__device__ int    g_span [BATCH][OUTT];

// ---------------------------------------------------------------------------
// Kernel 1: normalized knots -> span + Cox-de Boor basis per (batch, t)
// ---------------------------------------------------------------------------
__global__ void __launch_bounds__(OUTT) basis_kernel(const float* __restrict__ knot_u) {
    const int b = blockIdx.x;
    __shared__ float K[LKNOT];
    __shared__ float U[LKNOT];

    // Parallel coalesced load of raw knots (kills the serial DRAM chain).
    if (threadIdx.x < LKNOT) K[threadIdx.x] = knot_u[b * LKNOT + threadIdx.x];
    __syncthreads();

    if (threadIdx.x == 0) {
        float cs[LKNOT];
        float c = 0.0f;
        #pragma unroll
        for (int i = 0; i < LKNOT; i++) { c += K[i]; cs[i] = c; }
        const float c0  = cs[0];
        const float inv = 1.0f / (cs[LKNOT - 1] - c0);
        #pragma unroll
        for (int i = 0; i < LKNOT; i++) U[i] = (cs[i] - c0) * inv;
    }
    __syncthreads();

    const int   i    = threadIdx.x;           // eval point index 0..255
    const float step = (1.0f - 2e-5f) / (float)(OUTT - 1);
    const float t    = 1e-5f + (float)i * step;

    // find_span: first argmin over s in [DEG, LKNOT-DEG-1] of (d>1e-8 ? d : 1)
    float best = 1e30f;
    int   span = DEG;
    #pragma unroll 1
    for (int s = DEG; s <= LKNOT - DEG - 1; s++) {   // s = 3..64
        float d    = t - U[s];
        float cand = (d > 1e-8f) ? d : 1.0f;
        if (cand < best) { best = cand; span = s; }
    }

    // Cox-de Boor recursion (replicates reference op order).
    float Ni[DEG + 1];
    Ni[0] = 1.0f;
    #pragma unroll
    for (int k = 1; k <= DEG; k++) {
        float saved = 0.0f;
        #pragma unroll
        for (int r = 0; r < k; r++) {
            float K1   = U[span + r + 1];
            float K2   = U[span + 1 - k + r];
            float temp = Ni[r] / ((K1 - t) + (t - K2));
            Ni[r]      = saved + (K1 - t) * temp;
            saved      = (t - K2) * temp;
        }
        Ni[k] = saved;
    }

    g_span[b][i]  = span;
    g_basis[b][i] = make_float4(Ni[0], Ni[1], Ni[2], Ni[3]);
}

// ---------------------------------------------------------------------------
// Kernel 2: separable tensor-product evaluation.
// One block per (u, b). Stage the u-contracted row tmp[j] = sum_l Nu[l]*cp[su+l][j]
// (xyz only) in shared; each thread then does a 4-tap v contraction.
// ---------------------------------------------------------------------------
__global__ void __launch_bounds__(OUTT) eval_kernel(
    const float* __restrict__ ctrl, float* __restrict__ out) {
    const int u = blockIdx.x;
    const int b = blockIdx.y;
    const int v = threadIdx.x;

    __shared__ float tx[MCTRL + 4];   // pad so tmp[sv+r] never OOB-reads
    __shared__ float ty[MCTRL + 4];
    __shared__ float tz[MCTRL + 4];

    // u-axis contraction: 64 threads, one column each.
    if (v < MCTRL) {
        const float4 nu = g_basis[b][u];
        const int    su = g_span[b][u] - DEG;        // 0..60
        const float4* cp = (const float4*)ctrl
                         + (size_t)b * MCTRL * MCTRL + (size_t)su * MCTRL + v;
        float x, y, z;
        {
            float4 c0 = cp[0 * MCTRL];
            x = nu.x * c0.x; y = nu.x * c0.y; z = nu.x * c0.z;
        }
        {
            float4 c1 = cp[1 * MCTRL];
            x = fmaf(nu.y, c1.x, x); y = fmaf(nu.y, c1.y, y); z = fmaf(nu.y, c1.z, z);
        }
        {
            float4 c2 = cp[2 * MCTRL];
            x = fmaf(nu.z, c2.x, x); y = fmaf(nu.z, c2.y, y); z = fmaf(nu.z, c2.z, z);
        }
        {
            float4 c3 = cp[3 * MCTRL];
            x = fmaf(nu.w, c3.x, x); y = fmaf(nu.w, c3.y, y); z = fmaf(nu.w, c3.z, z);
        }
        tx[v] = x; ty[v] = y; tz[v] = z;
        if (v < 4) { tx[MCTRL + v] = 0.0f; ty[MCTRL + v] = 0.0f; tz[MCTRL + v] = 0.0f; }
    }

    // Per-thread v-axis basis + span (coalesced float4 loads).
    const float4 nv = g_basis[b][v];
    const int    sv = g_span[b][v] - DEG;            // 0..60

    __syncthreads();

    float ax = nv.x * tx[sv],     ay = nv.x * ty[sv],     az = nv.x * tz[sv];
    ax = fmaf(nv.y, tx[sv + 1], ax); ay = fmaf(nv.y, ty[sv + 1], ay); az = fmaf(nv.y, tz[sv + 1], az);
    ax = fmaf(nv.z, tx[sv + 2], ax); ay = fmaf(nv.z, ty[sv + 2], ay); az = fmaf(nv.z, tz[sv + 2], az);
    ax = fmaf(nv.w, tx[sv + 3], ax); ay = fmaf(nv.w, ty[sv + 3], ay); az = fmaf(nv.w, tz[sv + 3], az);

    float* o = out + ((size_t)(b * OUTT + u) * OUTT + v) * 3;
    o[0] = ax;
    o[1] = ay;
    o[2] = az;
}

// ---------------------------------------------------------------------------
extern "C" void kernel_launch(void* const* d_in, const int* in_sizes, int n_in,
                              void* d_out, int out_size) {
    const float* ctrl   = (const float*)d_in[0];   // [16,64,64,4]
    const float* knot_u = (const float*)d_in[1];   // [16,68]
    (void)in_sizes; (void)n_in; (void)out_size;

    float* out = (float*)d_out;                    // [16,256,256,3]

    basis_kernel<<<BATCH, OUTT>>>(knot_u);

    dim3 grid(OUTT, BATCH);
    eval_kernel<<<grid, OUTT>>>(ctrl, out);
}

// round 5
// speedup vs baseline: 1.6645x; 1.0191x over previous
#include <cuda_runtime.h>
#include <cuda_bf16.h>

// Problem constants (fixed by the reference)
#define BATCH 16
#define MCTRL 64          // control points per axis
#define DEG   3           // degree (P == Q == 3)
#define LKNOT 68          // M + P + 1
#define OUTT  256         // OUT_U == OUT_V
#define UBLK  8           // u-rows per eval block

// Basis values and spans for the shared u/v parameter axis.
// Reference builds V from knot_u and v-linspace == u-linspace, so
// Nv == Nu and vspan == uspan — compute once, use for both axes.
__device__ float4 g_basis[BATCH][OUTT];
__device__ int    g_span [BATCH][OUTT];

// ---------------------------------------------------------------------------
// Kernel 1: normalized knots -> span + Cox-de Boor basis per (batch, t)
// ---------------------------------------------------------------------------
__global__ void __launch_bounds__(OUTT) basis_kernel(const float* __restrict__ knot_u) {
    const int b   = blockIdx.x;
    const int tid = threadIdx.x;
    __shared__ float K[LKNOT];
    __shared__ float U[LKNOT];

    if (tid < LKNOT) K[tid] = knot_u[b * LKNOT + tid];
    __syncthreads();

    // Parallel cumsum: thread i sums K[0..i] (independent chains, no serial
    // thread-0 bottleneck).
    if (tid < LKNOT) {
        float c = 0.0f;
        #pragma unroll 1
        for (int j = 0; j <= tid; j++) c += K[j];
        U[tid] = c;
    }
    __syncthreads();
    const float c0  = U[0];
    const float inv = 1.0f / (U[LKNOT - 1] - c0);
    __syncthreads();
    if (tid < LKNOT) U[tid] = (U[tid] - c0) * inv;
    __syncthreads();

    const float step = (1.0f - 2e-5f) / (float)(OUTT - 1);
    const float t    = 1e-5f + (float)tid * step;

    // find_span: first argmin over s in [DEG, LKNOT-DEG-1] of (d>1e-8 ? d : 1)
    float best = 1e30f;
    int   span = DEG;
    #pragma unroll 1
    for (int s = DEG; s <= LKNOT - DEG - 1; s++) {   // s = 3..64
        float d    = t - U[s];
        float cand = (d > 1e-8f) ? d : 1.0f;
        if (cand < best) { best = cand; span = s; }
    }

    // Cox-de Boor recursion (replicates reference op order).
    float Ni[DEG + 1];
    Ni[0] = 1.0f;
    #pragma unroll
    for (int k = 1; k <= DEG; k++) {
        float saved = 0.0f;
        #pragma unroll
        for (int r = 0; r < k; r++) {
            float K1   = U[span + r + 1];
            float K2   = U[span + 1 - k + r];
            float temp = Ni[r] / ((K1 - t) + (t - K2));
            Ni[r]      = saved + (K1 - t) * temp;
            saved      = (t - K2) * temp;
        }
        Ni[k] = saved;
    }

    g_span[b][tid]  = span;
    g_basis[b][tid] = make_float4(Ni[0], Ni[1], Ni[2], Ni[3]);
}

// ---------------------------------------------------------------------------
// Kernel 2: separable tensor-product evaluation, 8 u-rows per block.
// Stage tmp[uu][j] = sum_l Nu[l]*cp[su+l][j] (xyz) in shared; each thread
// then does 8 independent 4-tap v contractions (ILP hides LDS latency).
// ---------------------------------------------------------------------------
__global__ void __launch_bounds__(OUTT) eval_kernel(
    const float* __restrict__ ctrl, float* __restrict__ out) {
    const int b   = blockIdx.y;
    const int u0  = blockIdx.x * UBLK;
    const int tid = threadIdx.x;

    __shared__ float ts[UBLK][3][MCTRL + 4];   // 8*3*68*4 = 6528 B

    // Staging: 8*64 = 512 (uu, col) pairs, 2 per thread.
    #pragma unroll
    for (int p = 0; p < (UBLK * MCTRL) / OUTT; p++) {
        const int idx = tid + p * OUTT;
        const int uu  = idx >> 6;           // 0..7
        const int j   = idx & 63;           // 0..63
        const float4 nu = g_basis[b][u0 + uu];
        const int    su = g_span[b][u0 + uu] - DEG;   // 0..60
        const float4* cp = (const float4*)ctrl
                         + (size_t)b * MCTRL * MCTRL + (size_t)su * MCTRL + j;
        const float4 c0 = cp[0 * MCTRL];
        const float4 c1 = cp[1 * MCTRL];
        const float4 c2 = cp[2 * MCTRL];
        const float4 c3 = cp[3 * MCTRL];
        float x = nu.x * c0.x, y = nu.x * c0.y, z = nu.x * c0.z;
        x = fmaf(nu.y, c1.x, x); y = fmaf(nu.y, c1.y, y); z = fmaf(nu.y, c1.z, z);
        x = fmaf(nu.z, c2.x, x); y = fmaf(nu.z, c2.y, y); z = fmaf(nu.z, c2.z, z);
        x = fmaf(nu.w, c3.x, x); y = fmaf(nu.w, c3.y, y); z = fmaf(nu.w, c3.z, z);
        ts[uu][0][j] = x; ts[uu][1][j] = y; ts[uu][2][j] = z;
    }
    // Pad tail (sv <= 60 analytically; keep reads in-bounds regardless).
    if (tid < UBLK * 4) {
        const int uu = tid >> 2, j = tid & 3;
        ts[uu][0][MCTRL + j] = 0.0f;
        ts[uu][1][MCTRL + j] = 0.0f;
        ts[uu][2][MCTRL + j] = 0.0f;
    }

    // Per-thread v-axis basis + span (coalesced loads, overlap with staging).
    const float4 nv = g_basis[b][tid];
    const int    sv = g_span[b][tid] - DEG;   // 0..60

    __syncthreads();

    float* obase = out + ((size_t)(b * OUTT + u0) * OUTT + tid) * 3;
    #pragma unroll
    for (int uu = 0; uu < UBLK; uu++) {
        const float* px = ts[uu][0];
        const float* py = ts[uu][1];
        const float* pz = ts[uu][2];
        float ax = nv.x * px[sv];
        float ay = nv.x * py[sv];
        float az = nv.x * pz[sv];
        ax = fmaf(nv.y, px[sv + 1], ax); ay = fmaf(nv.y, py[sv + 1], ay); az = fmaf(nv.y, pz[sv + 1], az);
        ax = fmaf(nv.z, px[sv + 2], ax); ay = fmaf(nv.z, py[sv + 2], ay); az = fmaf(nv.z, pz[sv + 2], az);
        ax = fmaf(nv.w, px[sv + 3], ax); ay = fmaf(nv.w, py[sv + 3], ay); az = fmaf(nv.w, pz[sv + 3], az);
        float* o = obase + (size_t)uu * OUTT * 3;
        o[0] = ax; o[1] = ay; o[2] = az;
    }
}

// ---------------------------------------------------------------------------
extern "C" void kernel_launch(void* const* d_in, const int* in_sizes, int n_in,
                              void* d_out, int out_size) {
    const float* ctrl   = (const float*)d_in[0];   // [16,64,64,4]
    const float* knot_u = (const float*)d_in[1];   // [16,68]
    (void)in_sizes; (void)n_in; (void)out_size;

    float* out = (float*)d_out;                    // [16,256,256,3]

    basis_kernel<<<BATCH, OUTT>>>(knot_u);

    dim3 grid(OUTT / UBLK, BATCH);
    eval_kernel<<<grid, OUTT>>>(ctrl, out);
}